// round 15
// baseline (speedup 1.0000x reference)
#include <cuda_runtime.h>
#include <cstdint>

// out[b] = a[b] @ x[b] : a [8,4096,4096] f32, x [8,4096,32] f32, out [8,4096,32] f32
// Round 15: persistent 444-CTA kernel (exactly 3/SM, one wave), static unit scheduler
// over 2048 (tile x k-quarter) units, pipeline rolls across unit boundaries
// (single prologue), STAGES=6 (72KB smem, up to 5 groups in flight),
// red.add flush per unit. Pre-permuted tf32 X; round-5 inner loop verbatim.

#define DEV __device__ __forceinline__

constexpr int Bsz = 8;
constexpr int Nn  = 4096;
constexpr int Dd  = 32;
constexpr int Kk  = 4096;

constexpr int BM  = 64;
constexpr int BK  = 32;
constexpr int THREADS = 128;
constexpr int STAGES = 6;

constexpr int CTAS  = 444;                  // 148 * 3, one even wave
constexpr int UIT   = 32;                   // iterations per unit (k-quarter)
constexpr int UNITS = (Nn / BM) * Bsz * 4;  // 512 tiles * 4 k-quarters = 2048
constexpr int BASE_UNITS = UNITS / CTAS;    // 4
constexpr int REM_UNITS  = UNITS - BASE_UNITS * CTAS; // 272

constexpr int A_STAGE_F = BM * BK;       // 2048 floats
constexpr int X_STAGE_F = BK * Dd;       // 1024 floats
constexpr int A_STAGE_B = A_STAGE_F * 4; // 8192 B
constexpr int X_STAGE_B = X_STAGE_F * 4; // 4096 B
constexpr int SMEM_BYTES = STAGES * (A_STAGE_B + X_STAGE_B); // 73728 B -> 3 CTAs/SM

// Permuted, tf32-rounded X: [b][kb(128)][ks(4)][lane(32)][8 floats], chunk-swizzled.
__device__ float g_xperm[Bsz * (Kk / BK) * X_STAGE_F];

DEV uint32_t cvta_s(const void* p) { return (uint32_t)__cvta_generic_to_shared(p); }
DEV void cp16(uint32_t dst, const void* src) {
    asm volatile("cp.async.cg.shared.global [%0], [%1], 16;\n" :: "r"(dst), "l"(src));
}
DEV void cp_commit() { asm volatile("cp.async.commit_group;\n" ::: "memory"); }

#define MMA_TF32(C, A0, A1, A2, A3, B0, B1)                                    \
    asm volatile(                                                              \
        "mma.sync.aligned.m16n8k8.row.col.f32.tf32.tf32.f32 "                  \
        "{%0,%1,%2,%3}, {%4,%5,%6,%7}, {%8,%9}, {%0,%1,%2,%3};\n"              \
        : "+f"(C[0]), "+f"(C[1]), "+f"(C[2]), "+f"(C[3])                       \
        : "r"(A0), "r"(A1), "r"(A2), "r"(A3), "r"(B0), "r"(B1))

// ---------------- tile-staged permute + rna-round X, fused out zero-init ----------------
__global__ void permute_x_kernel(const float* __restrict__ x, float4* __restrict__ outz) {
    __shared__ float tile[BK * Dd];
    const int t = blockIdx.x;                     // b*128 + kb
    const float* src = x + (size_t)t * (BK * Dd);
    float* dst = g_xperm + (size_t)t * X_STAGE_F;

    // zero out: 1M floats = 1024 blocks * 256 float4
    outz[blockIdx.x * 256 + threadIdx.x] = make_float4(0.f, 0.f, 0.f, 0.f);

#pragma unroll
    for (int i = threadIdx.x; i < BK * Dd; i += 256) tile[i] = src[i];
    __syncthreads();

#pragma unroll
    for (int i = threadIdx.x; i < X_STAGE_F; i += 256) {
        int w    = i & 3;
        int c    = (i >> 2) & 1;
        int lane = (i >> 3) & 31;
        int ks   = i >> 8;
        int s = (lane >> 2) & 1;
        int j = (c ^ s) * 4 + w;
        int tig = lane & 3, gid = lane >> 2;
        int kr = ks * 8 + tig + 4 * (j & 1);
        int d  = (j >> 1) * 8 + gid;
        uint32_t tt;
        asm("cvt.rna.tf32.f32 %0, %1;" : "=r"(tt) : "f"(tile[kr * Dd + d]));
        dst[i] = __uint_as_float(tt);
    }
}

// ---------------- persistent main GEMM ----------------
__global__ __launch_bounds__(THREADS)
void gsum_tf32_kernel(const float* __restrict__ a, float* __restrict__ out)
{
    extern __shared__ float smem[];
    float* As = smem;                        // [STAGES][A_STAGE_F], xor-swizzled rows
    float* Xs = smem + STAGES * A_STAGE_F;   // [STAGES][X_STAGE_F]
    const uint32_t As_base = cvta_s(As);
    const uint32_t Xs_base = cvta_s(Xs);

    const int tid  = threadIdx.x;
    const int warp = tid >> 5;
    const int lane = tid & 31;
    const int cta  = blockIdx.x;

    const int n_units = BASE_UNITS + (cta < REM_UNITS ? 1 : 0);
    const int total   = n_units * UIT;

    // per-thread constant offsets (floats for gmem, bytes for smem)
    int a_thr[4]; uint32_t a_off[4];
#pragma unroll
    for (int i = 0; i < 4; i++) {
        int idx = i * THREADS + tid;
        int row = idx >> 3, c4 = idx & 7;
        a_thr[i] = row * Kk + c4 * 4;
        a_off[i] = (uint32_t)((row * BK + ((c4 ^ (row & 7)) << 2)) * 4);
    }
    const int x_thr0 = tid * 4;
    const int x_thr1 = (128 + tid) * 4;
    const uint32_t x_off0 = (uint32_t)(tid * 16);
    const uint32_t x_off1 = (uint32_t)((128 + tid) * 16);

    float acc[4][4];
#pragma unroll
    for (int i = 0; i < 4; i++)
#pragma unroll
        for (int j = 0; j < 4; j++) acc[i][j] = 0.f;

    const int lm_row = (lane & 7) + (((lane >> 3) & 1) << 3);
    const int lm_g   = lane >> 4;
    const int a_row  = warp * 16 + lm_row;
    const uint32_t a_row_off = (uint32_t)(a_row * BK * 4);
    const int a_sw  = a_row & 7;

    const int tig = lane & 3;
    const int gid = lane >> 2;
    const int sx  = (lane >> 2) & 1;
    const uint32_t xA = (uint32_t)(lane * 32 + sx * 16);
    const uint32_t xB = (uint32_t)(lane * 32 + (16 ^ (sx * 16)));

    // unit decode: w = cta + CTAS*j ; tile t = w>>2, kq = w&3 ; b = t>>6, n0 = (t&63)*64
#define UNIT_BASES(j_, Ab_, Xb_)                                               \
    do {                                                                       \
        int w_ = cta + CTAS * (j_);                                            \
        int t_ = w_ >> 2, kq_ = w_ & 3;                                        \
        int b_ = t_ >> 6, nn_ = (t_ & 63) << 6;                                \
        Ab_ = ((size_t)(b_ * Nn + nn_)) * Kk + (size_t)kq_ * (UIT * BK);       \
        Xb_ = ((size_t)(b_ * (Kk / BK) + kq_ * UIT)) * X_STAGE_F;              \
    } while (0)

    // issue-stream state
    int ji = 0, li = 0;
    size_t AbI, XbI;
    UNIT_BASES(0, AbI, XbI);

#define ISSUE(buf_)                                                            \
    do {                                                                       \
        const float* ab_ = a + AbI + (size_t)li * BK;                          \
        const float* xb_ = g_xperm + XbI + (size_t)li * X_STAGE_F;             \
        uint32_t asb_ = As_base + (buf_) * A_STAGE_B;                          \
        uint32_t xsb_ = Xs_base + (buf_) * X_STAGE_B;                          \
        _Pragma("unroll")                                                      \
        for (int i_ = 0; i_ < 4; i_++)                                         \
            cp16(asb_ + a_off[i_], ab_ + a_thr[i_]);                           \
        cp16(xsb_ + x_off0, xb_ + x_thr0);                                     \
        cp16(xsb_ + x_off1, xb_ + x_thr1);                                     \
        cp_commit();                                                           \
    } while (0)

#define ADV_ISSUE()                                                            \
    do {                                                                       \
        if (++li == UIT) {                                                     \
            li = 0; ++ji;                                                      \
            if (ji < n_units) UNIT_BASES(ji, AbI, XbI);                        \
        }                                                                      \
    } while (0)

    // single prologue for the whole kernel: fill STAGES-1 stages
#pragma unroll
    for (int s = 0; s < STAGES - 1; ++s) { ISSUE(s); ADV_ISSUE(); }

    int cur = 0;
    int jc = 0, lc = 0;   // compute-stream unit / local iter
#pragma unroll 1
    for (int it = 0; it < total; ++it) {
        asm volatile("cp.async.wait_group %0;\n" :: "n"(STAGES - 2) : "memory");
        __syncthreads();

        if (it + STAGES - 1 < total) {
            int nbuf = cur == 0 ? STAGES - 1 : cur - 1;
            ISSUE(nbuf);
            ADV_ISSUE();
        } else {
            cp_commit();
        }

        const uint32_t a_cur = As_base + cur * A_STAGE_B + a_row_off;
        const uint32_t x_cur = Xs_base + cur * X_STAGE_B;

#pragma unroll
        for (int ks = 0; ks < 4; ++ks) {
            uint32_t ar[4];
            {
                int col4 = (ks * 2 + lm_g) ^ a_sw;
                asm volatile(
                    "ldmatrix.sync.aligned.m8n8.x4.shared.b16 {%0,%1,%2,%3}, [%4];\n"
                    : "=r"(ar[0]), "=r"(ar[1]), "=r"(ar[2]), "=r"(ar[3])
                    : "r"(a_cur + col4 * 16));
            }
            uint32_t at[4];
#pragma unroll
            for (int j = 0; j < 4; j++)
                asm("cvt.rna.tf32.f32 %0, %1;" : "=r"(at[j]) : "f"(__uint_as_float(ar[j])));

            uint32_t fr[8];
            {
                uint32_t base = x_cur + ks * 1024;
                asm volatile("ld.shared.v4.b32 {%0,%1,%2,%3}, [%4];\n"
                    : "=r"(fr[0]), "=r"(fr[1]), "=r"(fr[2]), "=r"(fr[3])
                    : "r"(base + xA));
                asm volatile("ld.shared.v4.b32 {%0,%1,%2,%3}, [%4];\n"
                    : "=r"(fr[4]), "=r"(fr[5]), "=r"(fr[6]), "=r"(fr[7])
                    : "r"(base + xB));
            }
#pragma unroll
            for (int ni = 0; ni < 4; ++ni)
                MMA_TF32(acc[ni], at[0], at[1], at[2], at[3], fr[2 * ni], fr[2 * ni + 1]);
        }
        cur = cur + 1 < STAGES ? cur + 1 : 0;

        // ---- per-unit flush: red.add partial tile, reset accumulators ----
        if (++lc == UIT) {
            lc = 0;
            int w_ = cta + CTAS * jc;
            int t_ = w_ >> 2;
            int b_ = t_ >> 6, nn_ = (t_ & 63) << 6;
            ++jc;
            const int orow = nn_ + warp * 16 + gid;
            float* ob = out + (size_t)b_ * Nn * Dd;
#pragma unroll
            for (int ni = 0; ni < 4; ++ni) {
                int col = ni * 8 + tig * 2;
                float* p0 = &ob[(size_t)orow * Dd + col];
                float* p1 = &ob[(size_t)(orow + 8) * Dd + col];
                asm volatile("red.global.add.f32 [%0], %1;\n" :: "l"(p0),     "f"(acc[ni][0]));
                asm volatile("red.global.add.f32 [%0], %1;\n" :: "l"(p0 + 1), "f"(acc[ni][1]));
                asm volatile("red.global.add.f32 [%0], %1;\n" :: "l"(p1),     "f"(acc[ni][2]));
                asm volatile("red.global.add.f32 [%0], %1;\n" :: "l"(p1 + 1), "f"(acc[ni][3]));
#pragma unroll
                for (int j = 0; j < 4; j++) acc[ni][j] = 0.f;
            }
        }
    }
}

extern "C" void kernel_launch(void* const* d_in, const int* in_sizes, int n_in,
                              void* d_out, int out_size)
{
    const float* x;
    const float* a;
    if (in_sizes[0] < in_sizes[1]) {
        x = (const float*)d_in[0];
        a = (const float*)d_in[1];
    } else {
        x = (const float*)d_in[1];
        a = (const float*)d_in[0];
    }
    float* out = (float*)d_out;

    permute_x_kernel<<<Bsz * (Kk / BK), 256>>>(x, (float4*)out);

    cudaFuncSetAttribute(gsum_tf32_kernel,
                         cudaFuncAttributeMaxDynamicSharedMemorySize, SMEM_BYTES);
    gsum_tf32_kernel<<<CTAS, THREADS, SMEM_BYTES>>>(a, out);
}